// round 13
// baseline (speedup 1.0000x reference)
#include <cuda_runtime.h>
#include <cuda_fp16.h>
#include <cstdint>

// ---------------------------------------------------------------------------
// RGCN conv with history cache.
//   out[n] = history_buffer[n]                       if history_map[n] != -1
//   out[n] = (1/deg) * sum_r A_r[n] @ W_r            otherwise
// Round 13: GEMM restructured for register-level fragment double-buffering
// (384 thr -> 170-reg ceiling); LDSM->MMA dependency stalls hidden.
// ---------------------------------------------------------------------------

#define MAX_NODE 100000
#define PAD_ROWS (MAX_NODE + 256)
#define HID 128
#define NUM_REL 8
#define KDIM (NUM_REL * HID)   // 1024

__device__ __half g_xh[(size_t)MAX_NODE * HID];   // x in fp16 (L2-resident)
__device__ __half g_Ah[(size_t)PAD_ROWS * KDIM];
__device__ __half g_Wh[(size_t)HID * KDIM];       // [n][k] (K-major)
__device__ int  g_active[MAX_NODE];
__device__ int  g_count;
__device__ int  g_is64;

// ======================= PTX helpers =======================================
__device__ __forceinline__ uint32_t smem_u32(const void* p) {
    uint32_t a;
    asm("{ .reg .u64 t; cvta.to.shared.u64 t, %1; cvt.u32.u64 %0, t; }"
        : "=r"(a) : "l"(p));
    return a;
}
#define CP16(dst, src) \
    asm volatile("cp.async.cg.shared.global [%0], [%1], 16;" \
        :: "r"(dst), "l"(src) : "memory")
#define CP_COMMIT() asm volatile("cp.async.commit_group;" ::: "memory")
#define CP_WAIT(n)  asm volatile("cp.async.wait_group %0;" :: "n"(n) : "memory")

#define LDSM4(r, a)                                                           \
    asm volatile("ldmatrix.sync.aligned.m8n8.x4.shared.b16 {%0,%1,%2,%3}, [%4];" \
        : "=r"((r)[0]), "=r"((r)[1]), "=r"((r)[2]), "=r"((r)[3]) : "r"(a))

#define MMA16816F16(c, a, b0, b1)                                             \
    asm volatile("mma.sync.aligned.m16n8k16.row.col.f32.f16.f16.f32 "         \
        "{%0,%1,%2,%3}, {%4,%5,%6,%7}, {%8,%9}, {%0,%1,%2,%3};"               \
        : "+f"((c)[0]), "+f"((c)[1]), "+f"((c)[2]), "+f"((c)[3])              \
        : "r"((a)[0]), "r"((a)[1]), "r"((a)[2]), "r"((a)[3]),                 \
          "r"(b0), "r"(b1))

// ===========================================================================
// Prep: reset/detect + W transpose->fp16 + x->fp16. One launch.
__global__ void prep_kernel(const float* __restrict__ W,
                            const float* __restrict__ x,
                            const void* __restrict__ ptrv,
                            int xq) {          // xq = num_node*HID/4
    int i = blockIdx.x * blockDim.x + threadIdx.x;
    if (i == 0) {
        g_count = 0;
        // ptr[0]==0; int64 -> word[1] is high half of 0; int32 -> deg>=1.
        g_is64 = (((const int*)ptrv)[1] == 0) ? 1 : 0;
    }
    if (i < xq) {
        float4 v = *(const float4*)(x + (size_t)i * 4);
        __half2 h01 = __floats2half2_rn(v.x, v.y);
        __half2 h23 = __floats2half2_rn(v.z, v.w);
        uint2 u;
        u.x = *(uint32_t*)&h01;
        u.y = *(uint32_t*)&h23;
        *(uint2*)(g_xh + (size_t)i * 4) = u;
    }
    if (i < KDIM * HID) {
        int k = i >> 7, n = i & 127;
        g_Wh[(size_t)n * KDIM + k] = __float2half(W[i]);
    }
}

// ---------------------------------------------------------------------------
__global__ void compact_history_kernel(const void* __restrict__ hmv,
                                       const float* __restrict__ hb,
                                       float* __restrict__ out,
                                       int dup, int num_node) {
    int w    = (int)((blockIdx.x * blockDim.x + threadIdx.x) >> 5);
    int lane = threadIdx.x & 31;
    if (w >= num_node) return;
    long long m = g_is64 ? ((const long long*)hmv)[w]
                         : (long long)((const int*)hmv)[w];
    if (m != -1LL) {
        float4 v = *(const float4*)(hb + (size_t)w * HID + lane * 4);
        *(float4*)(out + (size_t)w * HID + lane * 4) = v;
        if (dup)
            *(float4*)(out + (size_t)(w + num_node) * HID + lane * 4) = v;
    } else if (lane == 0) {
        int slot = atomicAdd(&g_count, 1);
        g_active[slot] = w;
    }
}

// ---------------------------------------------------------------------------
// Aggregate: one warp per node; fp16 gathers staged through smem (cp.async,
// 2 edges per warp-instruction, two pipelined groups of 8 edges).
__device__ __forceinline__ void store_h(float4 a, size_t off) {
    __half2 h01 = __floats2half2_rn(a.x, a.y);
    __half2 h23 = __floats2half2_rn(a.z, a.w);
    uint2 uh;
    uh.x = *(uint32_t*)&h01;
    uh.y = *(uint32_t*)&h23;
    *(uint2*)((__half*)g_Ah + off) = uh;
}

#define ACC_CASE(r, a)                                                        \
    case r: a.x += v_.x; a.y += v_.y; a.z += v_.z; a.w += v_.w; break;

#define AGG_CHUNK 16
#define AGG_ROWH  (AGG_CHUNK * HID)      // halfs per warp buffer (2048)
#define AGG_THREADS 128
#define AGG_WARPS   (AGG_THREADS / 32)
#define AGG_SMEM (AGG_WARPS * AGG_ROWH * 2)   // 16384 bytes

__global__ __launch_bounds__(AGG_THREADS)
void aggregate_kernel(const void* __restrict__ ptrv,
                      const void* __restrict__ idxv,
                      const void* __restrict__ etv) {
    extern __shared__ __half hbuf[];    // 4 warps * 16 rows * 256B = 16 KB
    int w    = (int)((blockIdx.x * blockDim.x + threadIdx.x) >> 5);
    int lane = threadIdx.x & 31;
    if (w >= g_count) return;
    int is64 = g_is64;
    int node = g_active[w];

    long long p0, p1;
    if (is64) {
        p0 = ((const long long*)ptrv)[node];
        p1 = ((const long long*)ptrv)[node + 1];
    } else {
        p0 = ((const int*)ptrv)[node];
        p1 = ((const int*)ptrv)[node + 1];
    }

    __half*  mybuf = hbuf + (size_t)(threadIdx.x >> 5) * AGG_ROWH;
    uint32_t sm    = smem_u32(mybuf);
    const __half* xh = (const __half*)g_xh;

    float4 a0 = {0,0,0,0}, a1 = {0,0,0,0}, a2 = {0,0,0,0}, a3 = {0,0,0,0};
    float4 a4 = {0,0,0,0}, a5 = {0,0,0,0}, a6 = {0,0,0,0}, a7 = {0,0,0,0};

    int hlf = lane >> 4;        // which of 2 edges this half-warp stages
    int ch16 = lane & 15;       // 16B chunk within 256B row

    for (long long c0 = p0; c0 < p1; c0 += AGG_CHUNK) {
        int n = (int)((p1 - c0) < AGG_CHUNK ? (p1 - c0) : AGG_CHUNK);
        long long s_l = 0; int t_l = 0;
        if (lane < n) {
            long long e = c0 + lane;
            s_l = is64 ? ((const long long*)idxv)[e]
                       : (long long)((const int*)idxv)[e];
            t_l = is64 ? (int)((const long long*)etv)[e]
                       : ((const int*)etv)[e];
        }
        if (n == AGG_CHUNK) {
            #pragma unroll
            for (int it = 0; it < 4; it++) {
                int e = it * 2 + hlf;
                long long src = __shfl_sync(0xffffffffu, s_l, e);
                CP16(sm + (uint32_t)(e * 256 + ch16 * 16),
                     xh + (size_t)src * HID + ch16 * 8);
            }
            CP_COMMIT();
            #pragma unroll
            for (int it = 4; it < 8; it++) {
                int e = it * 2 + hlf;
                long long src = __shfl_sync(0xffffffffu, s_l, e);
                CP16(sm + (uint32_t)(e * 256 + ch16 * 16),
                     xh + (size_t)src * HID + ch16 * 8);
            }
            CP_COMMIT();
            CP_WAIT(1);
            __syncwarp();
            #pragma unroll
            for (int e = 0; e < 8; e++) {
                int ty = __shfl_sync(0xffffffffu, t_l, e);
                uint2 u = *(const uint2*)(mybuf + e * HID + lane * 4);
                float2 f01 = __half22float2(*(__half2*)&u.x);
                float2 f23 = __half22float2(*(__half2*)&u.y);
                float4 v_ = make_float4(f01.x, f01.y, f23.x, f23.y);
                switch (ty) {
                    ACC_CASE(0, a0) ACC_CASE(1, a1) ACC_CASE(2, a2) ACC_CASE(3, a3)
                    ACC_CASE(4, a4) ACC_CASE(5, a5) ACC_CASE(6, a6) ACC_CASE(7, a7)
                    default: break;
                }
            }
            CP_WAIT(0);
            __syncwarp();
            #pragma unroll
            for (int e = 8; e < 16; e++) {
                int ty = __shfl_sync(0xffffffffu, t_l, e);
                uint2 u = *(const uint2*)(mybuf + e * HID + lane * 4);
                float2 f01 = __half22float2(*(__half2*)&u.x);
                float2 f23 = __half22float2(*(__half2*)&u.y);
                float4 v_ = make_float4(f01.x, f01.y, f23.x, f23.y);
                switch (ty) {
                    ACC_CASE(0, a0) ACC_CASE(1, a1) ACC_CASE(2, a2) ACC_CASE(3, a3)
                    ACC_CASE(4, a4) ACC_CASE(5, a5) ACC_CASE(6, a6) ACC_CASE(7, a7)
                    default: break;
                }
            }
        } else {
            for (int e = 0; e < n; e++) {
                long long src = __shfl_sync(0xffffffffu, s_l, e);
                int ty       = __shfl_sync(0xffffffffu, t_l, e);
                uint2 u = *(const uint2*)(xh + (size_t)src * HID + lane * 4);
                float2 f01 = __half22float2(*(__half2*)&u.x);
                float2 f23 = __half22float2(*(__half2*)&u.y);
                float4 v_ = make_float4(f01.x, f01.y, f23.x, f23.y);
                switch (ty) {
                    ACC_CASE(0, a0) ACC_CASE(1, a1) ACC_CASE(2, a2) ACC_CASE(3, a3)
                    ACC_CASE(4, a4) ACC_CASE(5, a5) ACC_CASE(6, a6) ACC_CASE(7, a7)
                    default: break;
                }
            }
        }
        __syncwarp();
    }

    size_t base = (size_t)w * KDIM + lane * 4;
    store_h(a0, base + 0 * HID);  store_h(a1, base + 1 * HID);
    store_h(a2, base + 2 * HID);  store_h(a3, base + 3 * HID);
    store_h(a4, base + 4 * HID);  store_h(a5, base + 5 * HID);
    store_h(a6, base + 6 * HID);  store_h(a7, base + 7 * HID);
}

// ---------------------------------------------------------------------------
// mma.sync GEMM: [count,1024](A fp16) @ [1024,128](W fp16), single term.
// CTA 192x128 (384 thr, 12 warps 3m x 4n, warp 64x32), k-tile 64, 3 stages,
// register-level fragment double-buffering (LDSM(ks+1) overlaps MMA(ks)).
#define GBM 192
#define GBK 64
#define NT (KDIM / GBK)                // 16 k-tiles
#define TPA (GBM * GBK * 2)            // 24576 bytes A tile
#define TPB (HID * GBK * 2)            // 16384 bytes B tile
#define S_AH 0
#define S_BH TPA
#define STAGE_B (TPA + TPB)            // 40960 per stage
#define NSTG 3
#define SMEM_BYTES (NSTG * STAGE_B)    // 122880

// swizzled byte offset within a [rows][64 f16] tile (row stride 128B, SW128)
__device__ __forceinline__ uint32_t swz(uint32_t row, uint32_t chunk) {
    return row * 128u + ((chunk ^ (row & 7u)) << 4);
}

__global__ __launch_bounds__(384, 1)
void gemm_mma_kernel(const void* __restrict__ ptrv,
                     float* __restrict__ out,
                     int dup, int num_node) {
    extern __shared__ __align__(1024) char smem[];
    int count = g_count;
    int m0 = blockIdx.x * GBM;
    if (m0 >= count) return;

    uint32_t sb = smem_u32(smem);
    int t = threadIdx.x, wid = t >> 5, lane = t & 31;
    int wm = wid >> 2;                 // 0..2  (m block of 64)
    int wn = wid & 3;                  // 0..3  (n block of 32)

    const __half* pAh = (const __half*)g_Ah;
    const __half* pWh = (const __half*)g_Wh;

    int ltile = lane >> 3, lrow = lane & 7;

    float acc[4][4][4];
    #pragma unroll
    for (int i = 0; i < 4; i++)
        #pragma unroll
        for (int j = 0; j < 4; j++)
            #pragma unroll
            for (int q = 0; q < 4; q++) acc[i][j][q] = 0.f;

    // double-buffered fragments
    uint32_t afr[2][4][4], bfr[2][2][4];

    auto load_stage = [&](int kt) {
        uint32_t stg = sb + (uint32_t)(kt % NSTG) * STAGE_B;
        size_t kofs = (size_t)kt * GBK;
        // A: 192 rows * 8 chunks = 1536 / 384 = 4 per thread
        #pragma unroll
        for (int i = 0; i < 4; i++) {
            int id  = t + i * 384;
            int row = id >> 3;              // 0..191
            int c   = id & 7;
            uint32_t sw = swz(row, c);
            size_t ga = (size_t)(m0 + row) * KDIM + kofs + c * 8;
            CP16(stg + S_AH + sw, pAh + ga);
        }
        // B: 128 rows * 8 chunks = 1024 loads
        #pragma unroll
        for (int i = 0; i < 3; i++) {
            int id = t + i * 384;
            if (id < 1024) {
                int row = id >> 3;
                int c   = id & 7;
                uint32_t sw = swz(row, c);
                size_t gw = (size_t)row * KDIM + kofs + c * 8;
                CP16(stg + S_BH + sw, pWh + gw);
            }
        }
        CP_COMMIT();
    };

    auto ldfrags = [&](int buf, int kt, int ks) {
        uint32_t stg = sb + (uint32_t)(kt % NSTG) * STAGE_B;
        int cch = ks * 2 + (ltile >> 1);
        #pragma unroll
        for (int j = 0; j < 2; j++) {
            uint32_t r = wn * 32 + j * 16 + (ltile & 1) * 8 + lrow;
            LDSM4(bfr[buf][j], stg + S_BH + swz(r, (uint32_t)cch));
        }
        #pragma unroll
        for (int mf = 0; mf < 4; mf++) {
            uint32_t r = wm * 64 + mf * 16 + (ltile & 1) * 8 + lrow;
            LDSM4(afr[buf][mf], stg + S_AH + swz(r, (uint32_t)cch));
        }
    };

    auto do_mma = [&](int buf) {
        #pragma unroll
        for (int mf = 0; mf < 4; mf++)
            #pragma unroll
            for (int nf = 0; nf < 4; nf++) {
                int hj = nf >> 1, ho = nf & 1;
                MMA16816F16(acc[mf][nf], afr[buf][mf],
                            bfr[buf][hj][ho], bfr[buf][hj][ho + 2]);
            }
    };

    load_stage(0);
    load_stage(1);
    CP_WAIT(1);                // stage 0 complete
    __syncthreads();

    int cur = 0;
    ldfrags(cur, 0, 0);

    for (int kt = 0; kt < NT; kt++) {
        if (kt + 2 < NT) load_stage(kt + 2);     // overwrites buf consumed @kt-1
        #pragma unroll
        for (int ks = 0; ks < 4; ks++) {
            if (ks < 3) {
                ldfrags(cur ^ 1, kt, ks + 1);    // overlap next frags with MMA
                do_mma(cur);
                cur ^= 1;
            } else {
                do_mma(cur);
            }
        }
        if (kt + 1 < NT) {
            if (kt + 2 < NT) { CP_WAIT(1); }     // stage kt+1 complete
            else             { CP_WAIT(0); }
            __syncthreads();                     // all warps done with stage kt
            ldfrags(cur, kt + 1, 0);
        }
    }

    // ---- epilogue: 1/deg scale + scatter (both output halves) ----
    int g  = lane >> 2;
    int tq = lane & 3;
    int is64 = g_is64;
    #pragma unroll
    for (int mf = 0; mf < 4; mf++) {
        int m_lo = m0 + wm * 64 + mf * 16 + g;       // rows g and g+8
        #pragma unroll
        for (int half = 0; half < 2; half++) {
            int m = m_lo + half * 8;
            if (m >= count) continue;
            int node = g_active[m];
            long long d;
            if (is64)
                d = ((const long long*)ptrv)[node + 1] - ((const long long*)ptrv)[node];
            else
                d = (long long)(((const int*)ptrv)[node + 1] - ((const int*)ptrv)[node]);
            float inv = 1.0f / (float)d;
            #pragma unroll
            for (int nf = 0; nf < 4; nf++) {
                float2 v;
                v.x = acc[mf][nf][half * 2 + 0] * inv;
                v.y = acc[mf][nf][half * 2 + 1] * inv;
                size_t co = (size_t)node * HID + wn * 32 + nf * 8 + tq * 2;
                *(float2*)(out + co) = v;
                if (dup)
                    *(float2*)(out + co + (size_t)num_node * HID) = v;
            }
        }
    }
}

// ---------------------------------------------------------------------------
extern "C" void kernel_launch(void* const* d_in, const int* in_sizes, int n_in,
                              void* d_out, int out_size) {
    const float* x  = (const float*)d_in[0];
    const float* W  = (const float*)d_in[1];   // [8,128,128] == [1024,128]
    const void*  pt = d_in[2];
    const void*  ix = d_in[3];
    const void*  et = d_in[4];
    const void*  hm = d_in[5];
    const float* hb = (const float*)d_in[6];
    float* out = (float*)d_out;

    int num_node = in_sizes[0] / HID;
    long long need2 = 2LL * (long long)num_node * HID;
    int dup = ((long long)out_size >= need2) ? 1 : 0;

    cudaFuncSetAttribute(gemm_mma_kernel,
                         cudaFuncAttributeMaxDynamicSharedMemorySize, SMEM_BYTES);
    cudaFuncSetAttribute(aggregate_kernel,
                         cudaFuncAttributeMaxDynamicSharedMemorySize, AGG_SMEM);

    int xq = num_node * HID / 4;
    int prep_blocks = (xq + 255) / 256;
    prep_kernel<<<prep_blocks, 256>>>(W, x, pt, xq);

    int warp_blocks = (num_node * 32 + 255) / 256;
    compact_history_kernel<<<warp_blocks, 256>>>(hm, hb, out, dup, num_node);

    int agg_blocks = (num_node * 32 + AGG_THREADS - 1) / AGG_THREADS;
    aggregate_kernel<<<agg_blocks, AGG_THREADS, AGG_SMEM>>>(pt, ix, et);

    gemm_mma_kernel<<<(num_node + GBM - 1) / GBM, 384, SMEM_BYTES>>>(
        pt, out, dup, num_node);
}

// round 14
// speedup vs baseline: 1.1798x; 1.1798x over previous
#include <cuda_runtime.h>
#include <cuda_fp16.h>
#include <cstdint>

// ---------------------------------------------------------------------------
// RGCN conv with history cache.
//   out[n] = history_buffer[n]                       if history_map[n] != -1
//   out[n] = (1/deg) * sum_r A_r[n] @ W_r            otherwise
// Round 14: GEMM reverted to round-12 (HMMA ceiling ~43us); x->fp16 conversion
// merged into compact_history; agg smem carveout maxed.
// ---------------------------------------------------------------------------

#define MAX_NODE 100000
#define PAD_ROWS (MAX_NODE + 256)
#define HID 128
#define NUM_REL 8
#define KDIM (NUM_REL * HID)   // 1024

__device__ __half g_xh[(size_t)MAX_NODE * HID];   // x in fp16 (L2-resident)
__device__ __half g_Ah[(size_t)PAD_ROWS * KDIM];
__device__ __half g_Wh[(size_t)HID * KDIM];       // [n][k] (K-major)
__device__ int  g_active[MAX_NODE];
__device__ int  g_count;
__device__ int  g_is64;

// ======================= PTX helpers =======================================
__device__ __forceinline__ uint32_t smem_u32(const void* p) {
    uint32_t a;
    asm("{ .reg .u64 t; cvta.to.shared.u64 t, %1; cvt.u32.u64 %0, t; }"
        : "=r"(a) : "l"(p));
    return a;
}
#define CP16(dst, src) \
    asm volatile("cp.async.cg.shared.global [%0], [%1], 16;" \
        :: "r"(dst), "l"(src) : "memory")
#define CP_COMMIT() asm volatile("cp.async.commit_group;" ::: "memory")
#define CP_WAIT(n)  asm volatile("cp.async.wait_group %0;" :: "n"(n) : "memory")

#define LDSM4(r, a)                                                           \
    asm volatile("ldmatrix.sync.aligned.m8n8.x4.shared.b16 {%0,%1,%2,%3}, [%4];" \
        : "=r"((r)[0]), "=r"((r)[1]), "=r"((r)[2]), "=r"((r)[3]) : "r"(a))

#define MMA16816F16(c, a, b0, b1)                                             \
    asm volatile("mma.sync.aligned.m16n8k16.row.col.f32.f16.f16.f32 "         \
        "{%0,%1,%2,%3}, {%4,%5,%6,%7}, {%8,%9}, {%0,%1,%2,%3};"               \
        : "+f"((c)[0]), "+f"((c)[1]), "+f"((c)[2]), "+f"((c)[3])              \
        : "r"((a)[0]), "r"((a)[1]), "r"((a)[2]), "r"((a)[3]),                 \
          "r"(b0), "r"(b1))

// ===========================================================================
// W prep (transpose [1024,128] fp32 -> [128][1024] fp16) + reset/detect.
__global__ void wprep_kernel(const float* __restrict__ W,
                             const void* __restrict__ ptrv) {
    int i = blockIdx.x * blockDim.x + threadIdx.x;
    if (i == 0) {
        g_count = 0;
        // ptr[0]==0; int64 -> word[1] is high half of 0; int32 -> deg>=1.
        g_is64 = (((const int*)ptrv)[1] == 0) ? 1 : 0;
    }
    if (i < KDIM * HID) {
        int k = i >> 7, n = i & 127;
        g_Wh[(size_t)n * KDIM + k] = __float2half(W[i]);
    }
}

// ---------------------------------------------------------------------------
// Merged: x->fp16 conversion + history copy + active compaction.
// One warp per node.
__global__ void compact_history_kernel(const float* __restrict__ x,
                                       const void* __restrict__ hmv,
                                       const float* __restrict__ hb,
                                       float* __restrict__ out,
                                       int dup, int num_node) {
    int w    = (int)((blockIdx.x * blockDim.x + threadIdx.x) >> 5);
    int lane = threadIdx.x & 31;
    if (w >= num_node) return;

    // x row -> fp16 (needed for every node: any node can be a gather source)
    {
        float4 v = *(const float4*)(x + (size_t)w * HID + lane * 4);
        __half2 h01 = __floats2half2_rn(v.x, v.y);
        __half2 h23 = __floats2half2_rn(v.z, v.w);
        uint2 u;
        u.x = *(uint32_t*)&h01;
        u.y = *(uint32_t*)&h23;
        *(uint2*)(g_xh + (size_t)w * HID + lane * 4) = u;
    }

    long long m = g_is64 ? ((const long long*)hmv)[w]
                         : (long long)((const int*)hmv)[w];
    if (m != -1LL) {
        float4 v = *(const float4*)(hb + (size_t)w * HID + lane * 4);
        *(float4*)(out + (size_t)w * HID + lane * 4) = v;
        if (dup)
            *(float4*)(out + (size_t)(w + num_node) * HID + lane * 4) = v;
    } else if (lane == 0) {
        int slot = atomicAdd(&g_count, 1);
        g_active[slot] = w;
    }
}

// ---------------------------------------------------------------------------
// Aggregate: one warp per node; fp16 gathers staged through smem (cp.async,
// 2 edges per warp-instruction, two pipelined groups of 8 edges).
__device__ __forceinline__ void store_h(float4 a, size_t off) {
    __half2 h01 = __floats2half2_rn(a.x, a.y);
    __half2 h23 = __floats2half2_rn(a.z, a.w);
    uint2 uh;
    uh.x = *(uint32_t*)&h01;
    uh.y = *(uint32_t*)&h23;
    *(uint2*)((__half*)g_Ah + off) = uh;
}

#define ACC_CASE(r, a)                                                        \
    case r: a.x += v_.x; a.y += v_.y; a.z += v_.z; a.w += v_.w; break;

#define AGG_CHUNK 16
#define AGG_ROWH  (AGG_CHUNK * HID)      // halfs per warp buffer (2048)
#define AGG_THREADS 128
#define AGG_WARPS   (AGG_THREADS / 32)
#define AGG_SMEM (AGG_WARPS * AGG_ROWH * 2)   // 16384 bytes

__global__ __launch_bounds__(AGG_THREADS)
void aggregate_kernel(const void* __restrict__ ptrv,
                      const void* __restrict__ idxv,
                      const void* __restrict__ etv) {
    extern __shared__ __half hbuf[];    // 4 warps * 16 rows * 256B = 16 KB
    int w    = (int)((blockIdx.x * blockDim.x + threadIdx.x) >> 5);
    int lane = threadIdx.x & 31;
    if (w >= g_count) return;
    int is64 = g_is64;
    int node = g_active[w];

    long long p0, p1;
    if (is64) {
        p0 = ((const long long*)ptrv)[node];
        p1 = ((const long long*)ptrv)[node + 1];
    } else {
        p0 = ((const int*)ptrv)[node];
        p1 = ((const int*)ptrv)[node + 1];
    }

    __half*  mybuf = hbuf + (size_t)(threadIdx.x >> 5) * AGG_ROWH;
    uint32_t sm    = smem_u32(mybuf);
    const __half* xh = (const __half*)g_xh;

    float4 a0 = {0,0,0,0}, a1 = {0,0,0,0}, a2 = {0,0,0,0}, a3 = {0,0,0,0};
    float4 a4 = {0,0,0,0}, a5 = {0,0,0,0}, a6 = {0,0,0,0}, a7 = {0,0,0,0};

    int hlf = lane >> 4;        // which of 2 edges this half-warp stages
    int ch16 = lane & 15;       // 16B chunk within 256B row

    for (long long c0 = p0; c0 < p1; c0 += AGG_CHUNK) {
        int n = (int)((p1 - c0) < AGG_CHUNK ? (p1 - c0) : AGG_CHUNK);
        long long s_l = 0; int t_l = 0;
        if (lane < n) {
            long long e = c0 + lane;
            s_l = is64 ? ((const long long*)idxv)[e]
                       : (long long)((const int*)idxv)[e];
            t_l = is64 ? (int)((const long long*)etv)[e]
                       : ((const int*)etv)[e];
        }
        if (n == AGG_CHUNK) {
            #pragma unroll
            for (int it = 0; it < 4; it++) {
                int e = it * 2 + hlf;
                long long src = __shfl_sync(0xffffffffu, s_l, e);
                CP16(sm + (uint32_t)(e * 256 + ch16 * 16),
                     xh + (size_t)src * HID + ch16 * 8);
            }
            CP_COMMIT();
            #pragma unroll
            for (int it = 4; it < 8; it++) {
                int e = it * 2 + hlf;
                long long src = __shfl_sync(0xffffffffu, s_l, e);
                CP16(sm + (uint32_t)(e * 256 + ch16 * 16),
                     xh + (size_t)src * HID + ch16 * 8);
            }
            CP_COMMIT();
            CP_WAIT(1);
            __syncwarp();
            #pragma unroll
            for (int e = 0; e < 8; e++) {
                int ty = __shfl_sync(0xffffffffu, t_l, e);
                uint2 u = *(const uint2*)(mybuf + e * HID + lane * 4);
                float2 f01 = __half22float2(*(__half2*)&u.x);
                float2 f23 = __half22float2(*(__half2*)&u.y);
                float4 v_ = make_float4(f01.x, f01.y, f23.x, f23.y);
                switch (ty) {
                    ACC_CASE(0, a0) ACC_CASE(1, a1) ACC_CASE(2, a2) ACC_CASE(3, a3)
                    ACC_CASE(4, a4) ACC_CASE(5, a5) ACC_CASE(6, a6) ACC_CASE(7, a7)
                    default: break;
                }
            }
            CP_WAIT(0);
            __syncwarp();
            #pragma unroll
            for (int e = 8; e < 16; e++) {
                int ty = __shfl_sync(0xffffffffu, t_l, e);
                uint2 u = *(const uint2*)(mybuf + e * HID + lane * 4);
                float2 f01 = __half22float2(*(__half2*)&u.x);
                float2 f23 = __half22float2(*(__half2*)&u.y);
                float4 v_ = make_float4(f01.x, f01.y, f23.x, f23.y);
                switch (ty) {
                    ACC_CASE(0, a0) ACC_CASE(1, a1) ACC_CASE(2, a2) ACC_CASE(3, a3)
                    ACC_CASE(4, a4) ACC_CASE(5, a5) ACC_CASE(6, a6) ACC_CASE(7, a7)
                    default: break;
                }
            }
        } else {
            for (int e = 0; e < n; e++) {
                long long src = __shfl_sync(0xffffffffu, s_l, e);
                int ty       = __shfl_sync(0xffffffffu, t_l, e);
                uint2 u = *(const uint2*)(xh + (size_t)src * HID + lane * 4);
                float2 f01 = __half22float2(*(__half2*)&u.x);
                float2 f23 = __half22float2(*(__half2*)&u.y);
                float4 v_ = make_float4(f01.x, f01.y, f23.x, f23.y);
                switch (ty) {
                    ACC_CASE(0, a0) ACC_CASE(1, a1) ACC_CASE(2, a2) ACC_CASE(3, a3)
                    ACC_CASE(4, a4) ACC_CASE(5, a5) ACC_CASE(6, a6) ACC_CASE(7, a7)
                    default: break;
                }
            }
        }
        __syncwarp();
    }

    size_t base = (size_t)w * KDIM + lane * 4;
    store_h(a0, base + 0 * HID);  store_h(a1, base + 1 * HID);
    store_h(a2, base + 2 * HID);  store_h(a3, base + 3 * HID);
    store_h(a4, base + 4 * HID);  store_h(a5, base + 5 * HID);
    store_h(a6, base + 6 * HID);  store_h(a7, base + 7 * HID);
}

// ---------------------------------------------------------------------------
// mma.sync GEMM: [count,1024](A fp16) @ [1024,128](W fp16), single term.
// CTA 128x128 (256 thr, 8 warps, warp 64x32), k-tile 64, 3-stage, 2 CTAs/SM.
#define GBM 128
#define GBK 64
#define NT (KDIM / GBK)                // 16 k-tiles
#define TPA (GBM * GBK * 2)            // 16384 bytes A tile
#define TPB (HID * GBK * 2)            // 16384 bytes B tile
#define S_AH 0
#define S_BH TPA
#define STAGE_B (TPA + TPB)            // 32768 per stage
#define NSTG 3
#define SMEM_BYTES (NSTG * STAGE_B)    // 98304 per CTA (x2 CTAs = 196608)

// swizzled byte offset within a [rows][64 f16] tile (row stride 128B, SW128)
__device__ __forceinline__ uint32_t swz(uint32_t row, uint32_t chunk) {
    return row * 128u + ((chunk ^ (row & 7u)) << 4);
}

__global__ __launch_bounds__(256, 2)
void gemm_mma_kernel(const void* __restrict__ ptrv,
                     float* __restrict__ out,
                     int dup, int num_node) {
    extern __shared__ __align__(1024) char smem[];
    int count = g_count;
    int m0 = blockIdx.x * GBM;
    if (m0 >= count) return;

    uint32_t sb = smem_u32(smem);
    int t = threadIdx.x, wid = t >> 5, lane = t & 31;
    int wm = wid >> 2;                 // 0..1  (m block of 64)
    int wn = wid & 3;                  // 0..3  (n block of 32)

    const __half* pAh = (const __half*)g_Ah;
    const __half* pWh = (const __half*)g_Wh;

    int ltile = lane >> 3, lrow = lane & 7;

    float acc[4][4][4];
    #pragma unroll
    for (int i = 0; i < 4; i++)
        #pragma unroll
        for (int j = 0; j < 4; j++)
            #pragma unroll
            for (int q = 0; q < 4; q++) acc[i][j][q] = 0.f;

    auto load_stage = [&](int kt) {
        uint32_t stg = sb + (uint32_t)(kt % NSTG) * STAGE_B;
        size_t kofs = (size_t)kt * GBK;
        #pragma unroll
        for (int i = 0; i < 4; i++) {
            int id  = t + i * 256;          // 0..1023
            int row = id >> 3;              // 0..127
            int c   = id & 7;
            uint32_t sw = swz(row, c);
            size_t ga = (size_t)(m0 + row) * KDIM + kofs + c * 8;
            CP16(stg + S_AH + sw, pAh + ga);
        }
        #pragma unroll
        for (int i = 0; i < 4; i++) {
            int id  = t + i * 256;          // 0..1023
            int row = id >> 3;              // 0..127
            int c   = id & 7;
            uint32_t sw = swz(row, c);
            size_t gw = (size_t)row * KDIM + kofs + c * 8;
            CP16(stg + S_BH + sw, pWh + gw);
        }
        CP_COMMIT();
    };

    load_stage(0);
    load_stage(1);

    for (int kt = 0; kt < NT; kt++) {
        if (kt + 2 < NT) { CP_WAIT(1); }          // stage kt complete
        else             { CP_WAIT(0); }          // drain at tail
        __syncthreads();                          // all warps past mma(kt-1)
        if (kt + 2 < NT) load_stage(kt + 2);      // reuse buf (kt-1)%3: safe

        uint32_t stg = sb + (uint32_t)(kt % NSTG) * STAGE_B;
        #pragma unroll
        for (int ks = 0; ks < 4; ks++) {
            int cch = ks * 2 + (ltile >> 1);
            uint32_t bh[2][4];
            #pragma unroll
            for (int j = 0; j < 2; j++) {
                uint32_t r = wn * 32 + j * 16 + (ltile & 1) * 8 + lrow;
                uint32_t sw = swz(r, (uint32_t)cch);
                LDSM4(bh[j], stg + S_BH + sw);
            }
            #pragma unroll
            for (int mf = 0; mf < 4; mf++) {
                uint32_t ah[4];
                uint32_t r = wm * 64 + mf * 16 + (ltile & 1) * 8 + lrow;
                uint32_t sw = swz(r, (uint32_t)cch);
                LDSM4(ah, stg + S_AH + sw);
                #pragma unroll
                for (int nf = 0; nf < 4; nf++) {
                    int hj = nf >> 1, ho = nf & 1;
                    MMA16816F16(acc[mf][nf], ah, bh[hj][ho], bh[hj][ho + 2]);
                }
            }
        }
    }

    // ---- epilogue: 1/deg scale + scatter (both output halves) ----
    int g  = lane >> 2;
    int tq = lane & 3;
    int is64 = g_is64;
    #pragma unroll
    for (int mf = 0; mf < 4; mf++) {
        int m_lo = m0 + wm * 64 + mf * 16 + g;       // rows g and g+8
        #pragma unroll
        for (int half = 0; half < 2; half++) {
            int m = m_lo + half * 8;
            if (m >= count) continue;
            int node = g_active[m];
            long long d;
            if (is64)
                d = ((const long long*)ptrv)[node + 1] - ((const long long*)ptrv)[node];
            else
                d = (long long)(((const int*)ptrv)[node + 1] - ((const int*)ptrv)[node]);
            float inv = 1.0f / (float)d;
            #pragma unroll
            for (int nf = 0; nf < 4; nf++) {
                float2 v;
                v.x = acc[mf][nf][half * 2 + 0] * inv;
                v.y = acc[mf][nf][half * 2 + 1] * inv;
                size_t co = (size_t)node * HID + wn * 32 + nf * 8 + tq * 2;
                *(float2*)(out + co) = v;
                if (dup)
                    *(float2*)(out + co + (size_t)num_node * HID) = v;
            }
        }
    }
}

// ---------------------------------------------------------------------------
extern "C" void kernel_launch(void* const* d_in, const int* in_sizes, int n_in,
                              void* d_out, int out_size) {
    const float* x  = (const float*)d_in[0];
    const float* W  = (const float*)d_in[1];   // [8,128,128] == [1024,128]
    const void*  pt = d_in[2];
    const void*  ix = d_in[3];
    const void*  et = d_in[4];
    const void*  hm = d_in[5];
    const float* hb = (const float*)d_in[6];
    float* out = (float*)d_out;

    int num_node = in_sizes[0] / HID;
    long long need2 = 2LL * (long long)num_node * HID;
    int dup = ((long long)out_size >= need2) ? 1 : 0;

    cudaFuncSetAttribute(gemm_mma_kernel,
                         cudaFuncAttributeMaxDynamicSharedMemorySize, SMEM_BYTES);
    cudaFuncSetAttribute(aggregate_kernel,
                         cudaFuncAttributeMaxDynamicSharedMemorySize, AGG_SMEM);
    cudaFuncSetAttribute(aggregate_kernel,
                         cudaFuncAttributePreferredSharedMemoryCarveout,
                         cudaSharedmemCarveoutMaxShared);

    wprep_kernel<<<(KDIM * HID + 255) / 256, 256>>>(W, pt);

    int warp_blocks = (num_node * 32 + 255) / 256;
    compact_history_kernel<<<warp_blocks, 256>>>(x, hm, hb, out, dup, num_node);

    int agg_blocks = (num_node * 32 + AGG_THREADS - 1) / AGG_THREADS;
    aggregate_kernel<<<agg_blocks, AGG_THREADS, AGG_SMEM>>>(pt, ix, et);

    gemm_mma_kernel<<<(num_node + GBM - 1) / GBM, 256, SMEM_BYTES>>>(
        pt, out, dup, num_node);
}

// round 15
// speedup vs baseline: 1.2097x; 1.0254x over previous
#include <cuda_runtime.h>
#include <cuda_fp16.h>
#include <cstdint>

// ---------------------------------------------------------------------------
// RGCN conv with history cache.
//   out[n] = history_buffer[n]                       if history_map[n] != -1
//   out[n] = (1/deg) * sum_r A_r[n] @ W_r            otherwise
// Round 15: GEMM warp tile 64x32 -> 64x64 (4 warps/CTA) to cut smem-port
// traffic 33%; W prep folded into compact; reset kernel shrunk to 1 warp.
// ---------------------------------------------------------------------------

#define MAX_NODE 100000
#define PAD_ROWS (MAX_NODE + 256)
#define HID 128
#define NUM_REL 8
#define KDIM (NUM_REL * HID)   // 1024

__device__ __half g_xh[(size_t)MAX_NODE * HID];   // x in fp16 (L2-resident)
__device__ __half g_Ah[(size_t)PAD_ROWS * KDIM];
__device__ __half g_Wh[(size_t)HID * KDIM];       // [n][k] (K-major)
__device__ int  g_active[MAX_NODE];
__device__ int  g_count;
__device__ int  g_is64;

// ======================= PTX helpers =======================================
__device__ __forceinline__ uint32_t smem_u32(const void* p) {
    uint32_t a;
    asm("{ .reg .u64 t; cvta.to.shared.u64 t, %1; cvt.u32.u64 %0, t; }"
        : "=r"(a) : "l"(p));
    return a;
}
#define CP16(dst, src) \
    asm volatile("cp.async.cg.shared.global [%0], [%1], 16;" \
        :: "r"(dst), "l"(src) : "memory")
#define CP_COMMIT() asm volatile("cp.async.commit_group;" ::: "memory")
#define CP_WAIT(n)  asm volatile("cp.async.wait_group %0;" :: "n"(n) : "memory")

#define LDSM4(r, a)                                                           \
    asm volatile("ldmatrix.sync.aligned.m8n8.x4.shared.b16 {%0,%1,%2,%3}, [%4];" \
        : "=r"((r)[0]), "=r"((r)[1]), "=r"((r)[2]), "=r"((r)[3]) : "r"(a))

#define MMA16816F16(c, a, b0, b1)                                             \
    asm volatile("mma.sync.aligned.m16n8k16.row.col.f32.f16.f16.f32 "         \
        "{%0,%1,%2,%3}, {%4,%5,%6,%7}, {%8,%9}, {%0,%1,%2,%3};"               \
        : "+f"((c)[0]), "+f"((c)[1]), "+f"((c)[2]), "+f"((c)[3])              \
        : "r"((a)[0]), "r"((a)[1]), "r"((a)[2]), "r"((a)[3]),                 \
          "r"(b0), "r"(b1))

// ===========================================================================
// Tiny reset: g_count/g_is64 only (1 warp).
__global__ void reset_kernel(const void* __restrict__ ptrv) {
    if (threadIdx.x == 0) {
        g_count = 0;
        // ptr[0]==0; int64 -> word[1] is high half of 0; int32 -> deg>=1.
        g_is64 = (((const int*)ptrv)[1] == 0) ? 1 : 0;
    }
}

// ---------------------------------------------------------------------------
// Merged: x->fp16 conversion + history copy + active compaction + W prep.
// One warp per node; first 512 blocks also transpose a slice of W to fp16.
__global__ void compact_history_kernel(const float* __restrict__ x,
                                       const void* __restrict__ hmv,
                                       const float* __restrict__ hb,
                                       const float* __restrict__ W,
                                       float* __restrict__ out,
                                       int dup, int num_node) {
    // W slice: blocks 0..511 each convert 256 elements of [1024,128] fp32.
    if (blockIdx.x < 512) {
        int i = blockIdx.x * 256 + threadIdx.x;
        int k = i >> 7, n = i & 127;
        g_Wh[(size_t)n * KDIM + k] = __float2half(W[i]);
    }

    int w    = (int)((blockIdx.x * blockDim.x + threadIdx.x) >> 5);
    int lane = threadIdx.x & 31;
    if (w >= num_node) return;

    // x row -> fp16 (needed for every node: any node can be a gather source)
    {
        float4 v = *(const float4*)(x + (size_t)w * HID + lane * 4);
        __half2 h01 = __floats2half2_rn(v.x, v.y);
        __half2 h23 = __floats2half2_rn(v.z, v.w);
        uint2 u;
        u.x = *(uint32_t*)&h01;
        u.y = *(uint32_t*)&h23;
        *(uint2*)(g_xh + (size_t)w * HID + lane * 4) = u;
    }

    long long m = g_is64 ? ((const long long*)hmv)[w]
                         : (long long)((const int*)hmv)[w];
    if (m != -1LL) {
        float4 v = *(const float4*)(hb + (size_t)w * HID + lane * 4);
        *(float4*)(out + (size_t)w * HID + lane * 4) = v;
        if (dup)
            *(float4*)(out + (size_t)(w + num_node) * HID + lane * 4) = v;
    } else if (lane == 0) {
        int slot = atomicAdd(&g_count, 1);
        g_active[slot] = w;
    }
}

// ---------------------------------------------------------------------------
// Aggregate: one warp per node; fp16 gathers staged through smem (cp.async,
// 2 edges per warp-instruction, two pipelined groups of 8 edges).
__device__ __forceinline__ void store_h(float4 a, size_t off) {
    __half2 h01 = __floats2half2_rn(a.x, a.y);
    __half2 h23 = __floats2half2_rn(a.z, a.w);
    uint2 uh;
    uh.x = *(uint32_t*)&h01;
    uh.y = *(uint32_t*)&h23;
    *(uint2*)((__half*)g_Ah + off) = uh;
}

#define ACC_CASE(r, a)                                                        \
    case r: a.x += v_.x; a.y += v_.y; a.z += v_.z; a.w += v_.w; break;

#define AGG_CHUNK 16
#define AGG_ROWH  (AGG_CHUNK * HID)      // halfs per warp buffer (2048)
#define AGG_THREADS 128
#define AGG_WARPS   (AGG_THREADS / 32)
#define AGG_SMEM (AGG_WARPS * AGG_ROWH * 2)   // 16384 bytes

__global__ __launch_bounds__(AGG_THREADS)
void aggregate_kernel(const void* __restrict__ ptrv,
                      const void* __restrict__ idxv,
                      const void* __restrict__ etv) {
    extern __shared__ __half hbuf[];    // 4 warps * 16 rows * 256B = 16 KB
    int w    = (int)((blockIdx.x * blockDim.x + threadIdx.x) >> 5);
    int lane = threadIdx.x & 31;
    if (w >= g_count) return;
    int is64 = g_is64;
    int node = g_active[w];

    long long p0, p1;
    if (is64) {
        p0 = ((const long long*)ptrv)[node];
        p1 = ((const long long*)ptrv)[node + 1];
    } else {
        p0 = ((const int*)ptrv)[node];
        p1 = ((const int*)ptrv)[node + 1];
    }

    __half*  mybuf = hbuf + (size_t)(threadIdx.x >> 5) * AGG_ROWH;
    uint32_t sm    = smem_u32(mybuf);
    const __half* xh = (const __half*)g_xh;

    float4 a0 = {0,0,0,0}, a1 = {0,0,0,0}, a2 = {0,0,0,0}, a3 = {0,0,0,0};
    float4 a4 = {0,0,0,0}, a5 = {0,0,0,0}, a6 = {0,0,0,0}, a7 = {0,0,0,0};

    int hlf = lane >> 4;        // which of 2 edges this half-warp stages
    int ch16 = lane & 15;       // 16B chunk within 256B row

    for (long long c0 = p0; c0 < p1; c0 += AGG_CHUNK) {
        int n = (int)((p1 - c0) < AGG_CHUNK ? (p1 - c0) : AGG_CHUNK);
        long long s_l = 0; int t_l = 0;
        if (lane < n) {
            long long e = c0 + lane;
            s_l = is64 ? ((const long long*)idxv)[e]
                       : (long long)((const int*)idxv)[e];
            t_l = is64 ? (int)((const long long*)etv)[e]
                       : ((const int*)etv)[e];
        }
        if (n == AGG_CHUNK) {
            #pragma unroll
            for (int it = 0; it < 4; it++) {
                int e = it * 2 + hlf;
                long long src = __shfl_sync(0xffffffffu, s_l, e);
                CP16(sm + (uint32_t)(e * 256 + ch16 * 16),
                     xh + (size_t)src * HID + ch16 * 8);
            }
            CP_COMMIT();
            #pragma unroll
            for (int it = 4; it < 8; it++) {
                int e = it * 2 + hlf;
                long long src = __shfl_sync(0xffffffffu, s_l, e);
                CP16(sm + (uint32_t)(e * 256 + ch16 * 16),
                     xh + (size_t)src * HID + ch16 * 8);
            }
            CP_COMMIT();
            CP_WAIT(1);
            __syncwarp();
            #pragma unroll
            for (int e = 0; e < 8; e++) {
                int ty = __shfl_sync(0xffffffffu, t_l, e);
                uint2 u = *(const uint2*)(mybuf + e * HID + lane * 4);
                float2 f01 = __half22float2(*(__half2*)&u.x);
                float2 f23 = __half22float2(*(__half2*)&u.y);
                float4 v_ = make_float4(f01.x, f01.y, f23.x, f23.y);
                switch (ty) {
                    ACC_CASE(0, a0) ACC_CASE(1, a1) ACC_CASE(2, a2) ACC_CASE(3, a3)
                    ACC_CASE(4, a4) ACC_CASE(5, a5) ACC_CASE(6, a6) ACC_CASE(7, a7)
                    default: break;
                }
            }
            CP_WAIT(0);
            __syncwarp();
            #pragma unroll
            for (int e = 8; e < 16; e++) {
                int ty = __shfl_sync(0xffffffffu, t_l, e);
                uint2 u = *(const uint2*)(mybuf + e * HID + lane * 4);
                float2 f01 = __half22float2(*(__half2*)&u.x);
                float2 f23 = __half22float2(*(__half2*)&u.y);
                float4 v_ = make_float4(f01.x, f01.y, f23.x, f23.y);
                switch (ty) {
                    ACC_CASE(0, a0) ACC_CASE(1, a1) ACC_CASE(2, a2) ACC_CASE(3, a3)
                    ACC_CASE(4, a4) ACC_CASE(5, a5) ACC_CASE(6, a6) ACC_CASE(7, a7)
                    default: break;
                }
            }
        } else {
            for (int e = 0; e < n; e++) {
                long long src = __shfl_sync(0xffffffffu, s_l, e);
                int ty       = __shfl_sync(0xffffffffu, t_l, e);
                uint2 u = *(const uint2*)(xh + (size_t)src * HID + lane * 4);
                float2 f01 = __half22float2(*(__half2*)&u.x);
                float2 f23 = __half22float2(*(__half2*)&u.y);
                float4 v_ = make_float4(f01.x, f01.y, f23.x, f23.y);
                switch (ty) {
                    ACC_CASE(0, a0) ACC_CASE(1, a1) ACC_CASE(2, a2) ACC_CASE(3, a3)
                    ACC_CASE(4, a4) ACC_CASE(5, a5) ACC_CASE(6, a6) ACC_CASE(7, a7)
                    default: break;
                }
            }
        }
        __syncwarp();
    }

    size_t base = (size_t)w * KDIM + lane * 4;
    store_h(a0, base + 0 * HID);  store_h(a1, base + 1 * HID);
    store_h(a2, base + 2 * HID);  store_h(a3, base + 3 * HID);
    store_h(a4, base + 4 * HID);  store_h(a5, base + 5 * HID);
    store_h(a6, base + 6 * HID);  store_h(a7, base + 7 * HID);
}

// ---------------------------------------------------------------------------
// mma.sync GEMM: [count,1024](A fp16) @ [1024,128](W fp16), single term.
// CTA 128x128, 128 threads (4 warps, 2m x 2n, warp 64x64), k-tile 64,
// 3-stage pipeline, 2 CTAs/SM. Warp tile 64x64 minimizes smem re-reads.
#define GBM 128
#define GBK 64
#define NT (KDIM / GBK)                // 16 k-tiles
#define TPA (GBM * GBK * 2)            // 16384 bytes A tile
#define TPB (HID * GBK * 2)            // 16384 bytes B tile
#define S_AH 0
#define S_BH TPA
#define STAGE_B (TPA + TPB)            // 32768 per stage
#define NSTG 3
#define SMEM_BYTES (NSTG * STAGE_B)    // 98304 per CTA (x2 CTAs = 196608)

// swizzled byte offset within a [rows][64 f16] tile (row stride 128B, SW128)
__device__ __forceinline__ uint32_t swz(uint32_t row, uint32_t chunk) {
    return row * 128u + ((chunk ^ (row & 7u)) << 4);
}

__global__ __launch_bounds__(128, 2)
void gemm_mma_kernel(const void* __restrict__ ptrv,
                     float* __restrict__ out,
                     int dup, int num_node) {
    extern __shared__ __align__(1024) char smem[];
    int count = g_count;
    int m0 = blockIdx.x * GBM;
    if (m0 >= count) return;

    uint32_t sb = smem_u32(smem);
    int t = threadIdx.x, wid = t >> 5, lane = t & 31;
    int wm = wid >> 1;                 // 0..1  (m block of 64)
    int wn = wid & 1;                  // 0..1  (n block of 64)

    const __half* pAh = (const __half*)g_Ah;
    const __half* pWh = (const __half*)g_Wh;

    int ltile = lane >> 3, lrow = lane & 7;

    // acc[mf][nf][4]: mf 0..3 (m16), nf 0..7 (n8)
    float acc[4][8][4];
    #pragma unroll
    for (int i = 0; i < 4; i++)
        #pragma unroll
        for (int j = 0; j < 8; j++)
            #pragma unroll
            for (int q = 0; q < 4; q++) acc[i][j][q] = 0.f;

    auto load_stage = [&](int kt) {
        uint32_t stg = sb + (uint32_t)(kt % NSTG) * STAGE_B;
        size_t kofs = (size_t)kt * GBK;
        // A: 128 rows x 8 chunks = 1024 CP16 / 128 thr = 8 each
        #pragma unroll
        for (int i = 0; i < 8; i++) {
            int id  = t + i * 128;
            int row = id >> 3;
            int c   = id & 7;
            uint32_t sw = swz(row, c);
            size_t ga = (size_t)(m0 + row) * KDIM + kofs + c * 8;
            CP16(stg + S_AH + sw, pAh + ga);
        }
        // B: 128 rows x 8 chunks = 1024 CP16
        #pragma unroll
        for (int i = 0; i < 8; i++) {
            int id  = t + i * 128;
            int row = id >> 3;
            int c   = id & 7;
            uint32_t sw = swz(row, c);
            size_t gw = (size_t)row * KDIM + kofs + c * 8;
            CP16(stg + S_BH + sw, pWh + gw);
        }
        CP_COMMIT();
    };

    load_stage(0);
    load_stage(1);

    for (int kt = 0; kt < NT; kt++) {
        if (kt + 2 < NT) { CP_WAIT(1); }          // stage kt complete
        else             { CP_WAIT(0); }          // drain at tail
        __syncthreads();                          // all warps past mma(kt-1)
        if (kt + 2 < NT) load_stage(kt + 2);      // reuse buf (kt-1)%3: safe

        uint32_t stg = sb + (uint32_t)(kt % NSTG) * STAGE_B;
        #pragma unroll
        for (int ks = 0; ks < 4; ks++) {
            int cch = ks * 2 + (ltile >> 1);
            // B fragments: 64 n-cols = 4 LDSM4 (each covers n16)
            uint32_t bh[4][4];
            #pragma unroll
            for (int j = 0; j < 4; j++) {
                uint32_t r = wn * 64 + j * 16 + (ltile & 1) * 8 + lrow;
                uint32_t sw = swz(r, (uint32_t)cch);
                LDSM4(bh[j], stg + S_BH + sw);
            }
            // A fragments + MMAs: 4 mf x 8 nf
            #pragma unroll
            for (int mf = 0; mf < 4; mf++) {
                uint32_t ah[4];
                uint32_t r = wm * 64 + mf * 16 + (ltile & 1) * 8 + lrow;
                uint32_t sw = swz(r, (uint32_t)cch);
                LDSM4(ah, stg + S_AH + sw);
                #pragma unroll
                for (int nf = 0; nf < 8; nf++) {
                    int hj = nf >> 1, ho = nf & 1;
                    MMA16816F16(acc[mf][nf], ah, bh[hj][ho], bh[hj][ho + 2]);
                }
            }
        }
    }

    // ---- epilogue: 1/deg scale + scatter (both output halves) ----
    int g  = lane >> 2;
    int tq = lane & 3;
    int is64 = g_is64;
    #pragma unroll
    for (int mf = 0; mf < 4; mf++) {
        int m_lo = m0 + wm * 64 + mf * 16 + g;       // rows g and g+8
        #pragma unroll
        for (int half = 0; half < 2; half++) {
            int m = m_lo + half * 8;
            if (m >= count) continue;
            int node = g_active[m];
            long long d;
            if (is64)
                d = ((const long long*)ptrv)[node + 1] - ((const long long*)ptrv)[node];
            else
                d = (long long)(((const int*)ptrv)[node + 1] - ((const int*)ptrv)[node]);
            float inv = 1.0f / (float)d;
            #pragma unroll
            for (int nf = 0; nf < 8; nf++) {
                float2 v;
                v.x = acc[mf][nf][half * 2 + 0] * inv;
                v.y = acc[mf][nf][half * 2 + 1] * inv;
                size_t co = (size_t)node * HID + wn * 64 + nf * 8 + tq * 2;
                *(float2*)(out + co) = v;
                if (dup)
                    *(float2*)(out + co + (size_t)num_node * HID) = v;
            }
        }
    }
}

// ---------------------------------------------------------------------------
extern "C" void kernel_launch(void* const* d_in, const int* in_sizes, int n_in,
                              void* d_out, int out_size) {
    const float* x  = (const float*)d_in[0];
    const float* W  = (const float*)d_in[1];   // [8,128,128] == [1024,128]
    const void*  pt = d_in[2];
    const void*  ix = d_in[3];
    const void*  et = d_in[4];
    const void*  hm = d_in[5];
    const float* hb = (const float*)d_in[6];
    float* out = (float*)d_out;

    int num_node = in_sizes[0] / HID;
    long long need2 = 2LL * (long long)num_node * HID;
    int dup = ((long long)out_size >= need2) ? 1 : 0;

    cudaFuncSetAttribute(gemm_mma_kernel,
                         cudaFuncAttributeMaxDynamicSharedMemorySize, SMEM_BYTES);
    cudaFuncSetAttribute(aggregate_kernel,
                         cudaFuncAttributeMaxDynamicSharedMemorySize, AGG_SMEM);
    cudaFuncSetAttribute(aggregate_kernel,
                         cudaFuncAttributePreferredSharedMemoryCarveout,
                         cudaSharedmemCarveoutMaxShared);

    reset_kernel<<<1, 32>>>(pt);

    int warp_blocks = (num_node * 32 + 255) / 256;
    compact_history_kernel<<<warp_blocks, 256>>>(x, hm, hb, W, out, dup, num_node);

    int agg_blocks = (num_node * 32 + AGG_THREADS - 1) / AGG_THREADS;
    aggregate_kernel<<<agg_blocks, AGG_THREADS, AGG_SMEM>>>(pt, ix, et);

    gemm_mma_kernel<<<(num_node + GBM - 1) / GBM, 128, SMEM_BYTES>>>(
        pt, out, dup, num_node);
}

// round 16
// speedup vs baseline: 1.2361x; 1.0218x over previous
#include <cuda_runtime.h>
#include <cuda_fp16.h>
#include <cstdint>

// ---------------------------------------------------------------------------
// RGCN conv with history cache.
//   out[n] = history_buffer[n]                       if history_map[n] != -1
//   out[n] = (1/deg) * sum_r A_r[n] @ W_r            otherwise
// Round 16: L2 residency management. Streaming (evict-first) hints on the
// write-once out stream and read-once x/hb streams, protecting g_xh/g_Ah
// residency in L2 for the aggregate gathers and GEMM A-reads.
// ---------------------------------------------------------------------------

#define MAX_NODE 100000
#define PAD_ROWS (MAX_NODE + 256)
#define HID 128
#define NUM_REL 8
#define KDIM (NUM_REL * HID)   // 1024

__device__ __half g_xh[(size_t)MAX_NODE * HID];   // x in fp16 (L2-resident)
__device__ __half g_Ah[(size_t)PAD_ROWS * KDIM];
__device__ __half g_Wh[(size_t)HID * KDIM];       // [n][k] (K-major)
__device__ int  g_active[MAX_NODE];
__device__ int  g_count;
__device__ int  g_is64;

// ======================= PTX helpers =======================================
__device__ __forceinline__ uint32_t smem_u32(const void* p) {
    uint32_t a;
    asm("{ .reg .u64 t; cvta.to.shared.u64 t, %1; cvt.u32.u64 %0, t; }"
        : "=r"(a) : "l"(p));
    return a;
}
#define CP16(dst, src) \
    asm volatile("cp.async.cg.shared.global [%0], [%1], 16;" \
        :: "r"(dst), "l"(src) : "memory")
#define CP_COMMIT() asm volatile("cp.async.commit_group;" ::: "memory")
#define CP_WAIT(n)  asm volatile("cp.async.wait_group %0;" :: "n"(n) : "memory")

#define LDSM4(r, a)                                                           \
    asm volatile("ldmatrix.sync.aligned.m8n8.x4.shared.b16 {%0,%1,%2,%3}, [%4];" \
        : "=r"((r)[0]), "=r"((r)[1]), "=r"((r)[2]), "=r"((r)[3]) : "r"(a))

#define MMA16816F16(c, a, b0, b1)                                             \
    asm volatile("mma.sync.aligned.m16n8k16.row.col.f32.f16.f16.f32 "         \
        "{%0,%1,%2,%3}, {%4,%5,%6,%7}, {%8,%9}, {%0,%1,%2,%3};"               \
        : "+f"((c)[0]), "+f"((c)[1]), "+f"((c)[2]), "+f"((c)[3])              \
        : "r"((a)[0]), "r"((a)[1]), "r"((a)[2]), "r"((a)[3]),                 \
          "r"(b0), "r"(b1))

// streaming (evict-first) float4 store/load
__device__ __forceinline__ void st_cs(float* p, float4 v) {
    asm volatile("st.global.cs.v4.f32 [%0], {%1,%2,%3,%4};"
        :: "l"(p), "f"(v.x), "f"(v.y), "f"(v.z), "f"(v.w) : "memory");
}
__device__ __forceinline__ void st_cs2(float* p, float2 v) {
    asm volatile("st.global.cs.v2.f32 [%0], {%1,%2};"
        :: "l"(p), "f"(v.x), "f"(v.y) : "memory");
}
__device__ __forceinline__ float4 ld_cs(const float* p) {
    float4 v;
    asm volatile("ld.global.cs.v4.f32 {%0,%1,%2,%3}, [%4];"
        : "=f"(v.x), "=f"(v.y), "=f"(v.z), "=f"(v.w) : "l"(p));
    return v;
}

// ===========================================================================
// Tiny reset: g_count/g_is64 only (1 warp).
__global__ void reset_kernel(const void* __restrict__ ptrv) {
    if (threadIdx.x == 0) {
        g_count = 0;
        // ptr[0]==0; int64 -> word[1] is high half of 0; int32 -> deg>=1.
        g_is64 = (((const int*)ptrv)[1] == 0) ? 1 : 0;
    }
}

// ---------------------------------------------------------------------------
// Merged: x->fp16 conversion + history copy + active compaction + W prep.
// One warp per node; first 512 blocks also transpose a slice of W to fp16.
__global__ void compact_history_kernel(const float* __restrict__ x,
                                       const void* __restrict__ hmv,
                                       const float* __restrict__ hb,
                                       const float* __restrict__ W,
                                       float* __restrict__ out,
                                       int dup, int num_node) {
    // W slice: blocks 0..511 each convert 256 elements of [1024,128] fp32.
    if (blockIdx.x < 512) {
        int i = blockIdx.x * 256 + threadIdx.x;
        int k = i >> 7, n = i & 127;
        g_Wh[(size_t)n * KDIM + k] = __float2half(W[i]);
    }

    int w    = (int)((blockIdx.x * blockDim.x + threadIdx.x) >> 5);
    int lane = threadIdx.x & 31;
    if (w >= num_node) return;

    // x row -> fp16 (read-once stream; keep xh cached, evict x)
    {
        float4 v = ld_cs(x + (size_t)w * HID + lane * 4);
        __half2 h01 = __floats2half2_rn(v.x, v.y);
        __half2 h23 = __floats2half2_rn(v.z, v.w);
        uint2 u;
        u.x = *(uint32_t*)&h01;
        u.y = *(uint32_t*)&h23;
        *(uint2*)(g_xh + (size_t)w * HID + lane * 4) = u;
    }

    long long m = g_is64 ? ((const long long*)hmv)[w]
                         : (long long)((const int*)hmv)[w];
    if (m != -1LL) {
        float4 v = ld_cs(hb + (size_t)w * HID + lane * 4);
        st_cs(out + (size_t)w * HID + lane * 4, v);
        if (dup)
            st_cs(out + (size_t)(w + num_node) * HID + lane * 4, v);
    } else if (lane == 0) {
        int slot = atomicAdd(&g_count, 1);
        g_active[slot] = w;
    }
}

// ---------------------------------------------------------------------------
// Aggregate: one warp per node; fp16 gathers staged through smem (cp.async,
// 2 edges per warp-instruction, two pipelined groups of 8 edges).
__device__ __forceinline__ void store_h(float4 a, size_t off) {
    __half2 h01 = __floats2half2_rn(a.x, a.y);
    __half2 h23 = __floats2half2_rn(a.z, a.w);
    uint2 uh;
    uh.x = *(uint32_t*)&h01;
    uh.y = *(uint32_t*)&h23;
    *(uint2*)((__half*)g_Ah + off) = uh;
}

#define ACC_CASE(r, a)                                                        \
    case r: a.x += v_.x; a.y += v_.y; a.z += v_.z; a.w += v_.w; break;

#define AGG_CHUNK 16
#define AGG_ROWH  (AGG_CHUNK * HID)      // halfs per warp buffer (2048)
#define AGG_THREADS 128
#define AGG_WARPS   (AGG_THREADS / 32)
#define AGG_SMEM (AGG_WARPS * AGG_ROWH * 2)   // 16384 bytes

__global__ __launch_bounds__(AGG_THREADS)
void aggregate_kernel(const void* __restrict__ ptrv,
                      const void* __restrict__ idxv,
                      const void* __restrict__ etv) {
    extern __shared__ __half hbuf[];    // 4 warps * 16 rows * 256B = 16 KB
    int w    = (int)((blockIdx.x * blockDim.x + threadIdx.x) >> 5);
    int lane = threadIdx.x & 31;
    if (w >= g_count) return;
    int is64 = g_is64;
    int node = g_active[w];

    long long p0, p1;
    if (is64) {
        p0 = ((const long long*)ptrv)[node];
        p1 = ((const long long*)ptrv)[node + 1];
    } else {
        p0 = ((const int*)ptrv)[node];
        p1 = ((const int*)ptrv)[node + 1];
    }

    __half*  mybuf = hbuf + (size_t)(threadIdx.x >> 5) * AGG_ROWH;
    uint32_t sm    = smem_u32(mybuf);
    const __half* xh = (const __half*)g_xh;

    float4 a0 = {0,0,0,0}, a1 = {0,0,0,0}, a2 = {0,0,0,0}, a3 = {0,0,0,0};
    float4 a4 = {0,0,0,0}, a5 = {0,0,0,0}, a6 = {0,0,0,0}, a7 = {0,0,0,0};

    int hlf = lane >> 4;        // which of 2 edges this half-warp stages
    int ch16 = lane & 15;       // 16B chunk within 256B row

    for (long long c0 = p0; c0 < p1; c0 += AGG_CHUNK) {
        int n = (int)((p1 - c0) < AGG_CHUNK ? (p1 - c0) : AGG_CHUNK);
        long long s_l = 0; int t_l = 0;
        if (lane < n) {
            long long e = c0 + lane;
            s_l = is64 ? ((const long long*)idxv)[e]
                       : (long long)((const int*)idxv)[e];
            t_l = is64 ? (int)((const long long*)etv)[e]
                       : ((const int*)etv)[e];
        }
        if (n == AGG_CHUNK) {
            #pragma unroll
            for (int it = 0; it < 4; it++) {
                int e = it * 2 + hlf;
                long long src = __shfl_sync(0xffffffffu, s_l, e);
                CP16(sm + (uint32_t)(e * 256 + ch16 * 16),
                     xh + (size_t)src * HID + ch16 * 8);
            }
            CP_COMMIT();
            #pragma unroll
            for (int it = 4; it < 8; it++) {
                int e = it * 2 + hlf;
                long long src = __shfl_sync(0xffffffffu, s_l, e);
                CP16(sm + (uint32_t)(e * 256 + ch16 * 16),
                     xh + (size_t)src * HID + ch16 * 8);
            }
            CP_COMMIT();
            CP_WAIT(1);
            __syncwarp();
            #pragma unroll
            for (int e = 0; e < 8; e++) {
                int ty = __shfl_sync(0xffffffffu, t_l, e);
                uint2 u = *(const uint2*)(mybuf + e * HID + lane * 4);
                float2 f01 = __half22float2(*(__half2*)&u.x);
                float2 f23 = __half22float2(*(__half2*)&u.y);
                float4 v_ = make_float4(f01.x, f01.y, f23.x, f23.y);
                switch (ty) {
                    ACC_CASE(0, a0) ACC_CASE(1, a1) ACC_CASE(2, a2) ACC_CASE(3, a3)
                    ACC_CASE(4, a4) ACC_CASE(5, a5) ACC_CASE(6, a6) ACC_CASE(7, a7)
                    default: break;
                }
            }
            CP_WAIT(0);
            __syncwarp();
            #pragma unroll
            for (int e = 8; e < 16; e++) {
                int ty = __shfl_sync(0xffffffffu, t_l, e);
                uint2 u = *(const uint2*)(mybuf + e * HID + lane * 4);
                float2 f01 = __half22float2(*(__half2*)&u.x);
                float2 f23 = __half22float2(*(__half2*)&u.y);
                float4 v_ = make_float4(f01.x, f01.y, f23.x, f23.y);
                switch (ty) {
                    ACC_CASE(0, a0) ACC_CASE(1, a1) ACC_CASE(2, a2) ACC_CASE(3, a3)
                    ACC_CASE(4, a4) ACC_CASE(5, a5) ACC_CASE(6, a6) ACC_CASE(7, a7)
                    default: break;
                }
            }
        } else {
            for (int e = 0; e < n; e++) {
                long long src = __shfl_sync(0xffffffffu, s_l, e);
                int ty       = __shfl_sync(0xffffffffu, t_l, e);
                uint2 u = *(const uint2*)(xh + (size_t)src * HID + lane * 4);
                float2 f01 = __half22float2(*(__half2*)&u.x);
                float2 f23 = __half22float2(*(__half2*)&u.y);
                float4 v_ = make_float4(f01.x, f01.y, f23.x, f23.y);
                switch (ty) {
                    ACC_CASE(0, a0) ACC_CASE(1, a1) ACC_CASE(2, a2) ACC_CASE(3, a3)
                    ACC_CASE(4, a4) ACC_CASE(5, a5) ACC_CASE(6, a6) ACC_CASE(7, a7)
                    default: break;
                }
            }
        }
        __syncwarp();
    }

    size_t base = (size_t)w * KDIM + lane * 4;
    store_h(a0, base + 0 * HID);  store_h(a1, base + 1 * HID);
    store_h(a2, base + 2 * HID);  store_h(a3, base + 3 * HID);
    store_h(a4, base + 4 * HID);  store_h(a5, base + 5 * HID);
    store_h(a6, base + 6 * HID);  store_h(a7, base + 7 * HID);
}

// ---------------------------------------------------------------------------
// mma.sync GEMM: [count,1024](A fp16) @ [1024,128](W fp16), single term.
// CTA 128x128, 128 threads (4 warps, 2m x 2n, warp 64x64), k-tile 64,
// 3-stage pipeline, 2 CTAs/SM.
#define GBM 128
#define GBK 64
#define NT (KDIM / GBK)                // 16 k-tiles
#define TPA (GBM * GBK * 2)            // 16384 bytes A tile
#define TPB (HID * GBK * 2)            // 16384 bytes B tile
#define S_AH 0
#define S_BH TPA
#define STAGE_B (TPA + TPB)            // 32768 per stage
#define NSTG 3
#define SMEM_BYTES (NSTG * STAGE_B)    // 98304 per CTA (x2 CTAs = 196608)

// swizzled byte offset within a [rows][64 f16] tile (row stride 128B, SW128)
__device__ __forceinline__ uint32_t swz(uint32_t row, uint32_t chunk) {
    return row * 128u + ((chunk ^ (row & 7u)) << 4);
}

__global__ __launch_bounds__(128, 2)
void gemm_mma_kernel(const void* __restrict__ ptrv,
                     float* __restrict__ out,
                     int dup, int num_node) {
    extern __shared__ __align__(1024) char smem[];
    int count = g_count;
    int m0 = blockIdx.x * GBM;
    if (m0 >= count) return;

    uint32_t sb = smem_u32(smem);
    int t = threadIdx.x, wid = t >> 5, lane = t & 31;
    int wm = wid >> 1;                 // 0..1  (m block of 64)
    int wn = wid & 1;                  // 0..1  (n block of 64)

    const __half* pAh = (const __half*)g_Ah;
    const __half* pWh = (const __half*)g_Wh;

    int ltile = lane >> 3, lrow = lane & 7;

    float acc[4][8][4];
    #pragma unroll
    for (int i = 0; i < 4; i++)
        #pragma unroll
        for (int j = 0; j < 8; j++)
            #pragma unroll
            for (int q = 0; q < 4; q++) acc[i][j][q] = 0.f;

    auto load_stage = [&](int kt) {
        uint32_t stg = sb + (uint32_t)(kt % NSTG) * STAGE_B;
        size_t kofs = (size_t)kt * GBK;
        #pragma unroll
        for (int i = 0; i < 8; i++) {
            int id  = t + i * 128;
            int row = id >> 3;
            int c   = id & 7;
            uint32_t sw = swz(row, c);
            size_t ga = (size_t)(m0 + row) * KDIM + kofs + c * 8;
            CP16(stg + S_AH + sw, pAh + ga);
        }
        #pragma unroll
        for (int i = 0; i < 8; i++) {
            int id  = t + i * 128;
            int row = id >> 3;
            int c   = id & 7;
            uint32_t sw = swz(row, c);
            size_t gw = (size_t)row * KDIM + kofs + c * 8;
            CP16(stg + S_BH + sw, pWh + gw);
        }
        CP_COMMIT();
    };

    load_stage(0);
    load_stage(1);

    for (int kt = 0; kt < NT; kt++) {
        if (kt + 2 < NT) { CP_WAIT(1); }          // stage kt complete
        else             { CP_WAIT(0); }          // drain at tail
        __syncthreads();                          // all warps past mma(kt-1)
        if (kt + 2 < NT) load_stage(kt + 2);      // reuse buf (kt-1)%3: safe

        uint32_t stg = sb + (uint32_t)(kt % NSTG) * STAGE_B;
        #pragma unroll
        for (int ks = 0; ks < 4; ks++) {
            int cch = ks * 2 + (ltile >> 1);
            uint32_t bh[4][4];
            #pragma unroll
            for (int j = 0; j < 4; j++) {
                uint32_t r = wn * 64 + j * 16 + (ltile & 1) * 8 + lrow;
                uint32_t sw = swz(r, (uint32_t)cch);
                LDSM4(bh[j], stg + S_BH + sw);
            }
            #pragma unroll
            for (int mf = 0; mf < 4; mf++) {
                uint32_t ah[4];
                uint32_t r = wm * 64 + mf * 16 + (ltile & 1) * 8 + lrow;
                uint32_t sw = swz(r, (uint32_t)cch);
                LDSM4(ah, stg + S_AH + sw);
                #pragma unroll
                for (int nf = 0; nf < 8; nf++) {
                    int hj = nf >> 1, ho = nf & 1;
                    MMA16816F16(acc[mf][nf], ah, bh[hj][ho], bh[hj][ho + 2]);
                }
            }
        }
    }

    // ---- epilogue: 1/deg scale + scatter (streaming stores) ----
    int g  = lane >> 2;
    int tq = lane & 3;
    int is64 = g_is64;
    #pragma unroll
    for (int mf = 0; mf < 4; mf++) {
        int m_lo = m0 + wm * 64 + mf * 16 + g;       // rows g and g+8
        #pragma unroll
        for (int half = 0; half < 2; half++) {
            int m = m_lo + half * 8;
            if (m >= count) continue;
            int node = g_active[m];
            long long d;
            if (is64)
                d = ((const long long*)ptrv)[node + 1] - ((const long long*)ptrv)[node];
            else
                d = (long long)(((const int*)ptrv)[node + 1] - ((const int*)ptrv)[node]);
            float inv = 1.0f / (float)d;
            #pragma unroll
            for (int nf = 0; nf < 8; nf++) {
                float2 v;
                v.x = acc[mf][nf][half * 2 + 0] * inv;
                v.y = acc[mf][nf][half * 2 + 1] * inv;
                size_t co = (size_t)node * HID + wn * 64 + nf * 8 + tq * 2;
                st_cs2(out + co, v);
                if (dup)
                    st_cs2(out + co + (size_t)num_node * HID, v);
            }
        }
    }
}

// ---------------------------------------------------------------------------
extern "C" void kernel_launch(void* const* d_in, const int* in_sizes, int n_in,
                              void* d_out, int out_size) {
    const float* x  = (const float*)d_in[0];
    const float* W  = (const float*)d_in[1];   // [8,128,128] == [1024,128]
    const void*  pt = d_in[2];
    const void*  ix = d_in[3];
    const void*  et = d_in[4];
    const void*  hm = d_in[5];
    const float* hb = (const float*)d_in[6];
    float* out = (float*)d_out;

    int num_node = in_sizes[0] / HID;
    long long need2 = 2LL * (long long)num_node * HID;
    int dup = ((long long)out_size >= need2) ? 1 : 0;

    cudaFuncSetAttribute(gemm_mma_kernel,
                         cudaFuncAttributeMaxDynamicSharedMemorySize, SMEM_BYTES);
    cudaFuncSetAttribute(aggregate_kernel,
                         cudaFuncAttributeMaxDynamicSharedMemorySize, AGG_SMEM);
    cudaFuncSetAttribute(aggregate_kernel,
                         cudaFuncAttributePreferredSharedMemoryCarveout,
                         cudaSharedmemCarveoutMaxShared);

    reset_kernel<<<1, 32>>>(pt);

    int warp_blocks = (num_node * 32 + 255) / 256;
    compact_history_kernel<<<warp_blocks, 256>>>(x, hm, hb, W, out, dup, num_node);

    int agg_blocks = (num_node * 32 + AGG_THREADS - 1) / AGG_THREADS;
    aggregate_kernel<<<agg_blocks, AGG_THREADS, AGG_SMEM>>>(pt, ix, et);

    gemm_mma_kernel<<<(num_node + GBM - 1) / GBM, 128, SMEM_BYTES>>>(
        pt, out, dup, num_node);
}

// round 17
// speedup vs baseline: 1.2453x; 1.0075x over previous
#include <cuda_runtime.h>
#include <cuda_fp16.h>
#include <cstdint>

// ---------------------------------------------------------------------------
// RGCN conv with history cache.
//   out[n] = history_buffer[n]                       if history_map[n] != -1
//   out[n] = (1/deg) * sum_r A_r[n] @ W_r            otherwise
// Round 17: GEMM fragment software pipeline (double-buffered A and B frags,
// LDSM(next) issued before MMA(current)) inside the 128-thr/2-CTA config
// whose 256-reg ceiling can afford it.
// ---------------------------------------------------------------------------

#define MAX_NODE 100000
#define PAD_ROWS (MAX_NODE + 256)
#define HID 128
#define NUM_REL 8
#define KDIM (NUM_REL * HID)   // 1024

__device__ __half g_xh[(size_t)MAX_NODE * HID];   // x in fp16 (L2-resident)
__device__ __half g_Ah[(size_t)PAD_ROWS * KDIM];
__device__ __half g_Wh[(size_t)HID * KDIM];       // [n][k] (K-major)
__device__ int  g_active[MAX_NODE];
__device__ int  g_count;
__device__ int  g_is64;

// ======================= PTX helpers =======================================
__device__ __forceinline__ uint32_t smem_u32(const void* p) {
    uint32_t a;
    asm("{ .reg .u64 t; cvta.to.shared.u64 t, %1; cvt.u32.u64 %0, t; }"
        : "=r"(a) : "l"(p));
    return a;
}
#define CP16(dst, src) \
    asm volatile("cp.async.cg.shared.global [%0], [%1], 16;" \
        :: "r"(dst), "l"(src) : "memory")
#define CP_COMMIT() asm volatile("cp.async.commit_group;" ::: "memory")
#define CP_WAIT(n)  asm volatile("cp.async.wait_group %0;" :: "n"(n) : "memory")

#define LDSM4(r, a)                                                           \
    asm volatile("ldmatrix.sync.aligned.m8n8.x4.shared.b16 {%0,%1,%2,%3}, [%4];" \
        : "=r"((r)[0]), "=r"((r)[1]), "=r"((r)[2]), "=r"((r)[3]) : "r"(a))

#define MMA16816F16(c, a, b0, b1)                                             \
    asm volatile("mma.sync.aligned.m16n8k16.row.col.f32.f16.f16.f32 "         \
        "{%0,%1,%2,%3}, {%4,%5,%6,%7}, {%8,%9}, {%0,%1,%2,%3};"               \
        : "+f"((c)[0]), "+f"((c)[1]), "+f"((c)[2]), "+f"((c)[3])              \
        : "r"((a)[0]), "r"((a)[1]), "r"((a)[2]), "r"((a)[3]),                 \
          "r"(b0), "r"(b1))

// streaming (evict-first) float4 store/load
__device__ __forceinline__ void st_cs(float* p, float4 v) {
    asm volatile("st.global.cs.v4.f32 [%0], {%1,%2,%3,%4};"
        :: "l"(p), "f"(v.x), "f"(v.y), "f"(v.z), "f"(v.w) : "memory");
}
__device__ __forceinline__ void st_cs2(float* p, float2 v) {
    asm volatile("st.global.cs.v2.f32 [%0], {%1,%2};"
        :: "l"(p), "f"(v.x), "f"(v.y) : "memory");
}
__device__ __forceinline__ float4 ld_cs(const float* p) {
    float4 v;
    asm volatile("ld.global.cs.v4.f32 {%0,%1,%2,%3}, [%4];"
        : "=f"(v.x), "=f"(v.y), "=f"(v.z), "=f"(v.w) : "l"(p));
    return v;
}

// ===========================================================================
// Tiny reset: g_count/g_is64 only (1 warp).
__global__ void reset_kernel(const void* __restrict__ ptrv) {
    if (threadIdx.x == 0) {
        g_count = 0;
        // ptr[0]==0; int64 -> word[1] is high half of 0; int32 -> deg>=1.
        g_is64 = (((const int*)ptrv)[1] == 0) ? 1 : 0;
    }
}

// ---------------------------------------------------------------------------
// Merged: x->fp16 conversion + history copy + active compaction + W prep.
__global__ void compact_history_kernel(const float* __restrict__ x,
                                       const void* __restrict__ hmv,
                                       const float* __restrict__ hb,
                                       const float* __restrict__ W,
                                       float* __restrict__ out,
                                       int dup, int num_node) {
    // W slice: blocks 0..511 each convert 256 elements of [1024,128] fp32.
    if (blockIdx.x < 512) {
        int i = blockIdx.x * 256 + threadIdx.x;
        int k = i >> 7, n = i & 127;
        g_Wh[(size_t)n * KDIM + k] = __float2half(W[i]);
    }

    int w    = (int)((blockIdx.x * blockDim.x + threadIdx.x) >> 5);
    int lane = threadIdx.x & 31;
    if (w >= num_node) return;

    // x row -> fp16 (read-once stream; keep xh cached, evict x)
    {
        float4 v = ld_cs(x + (size_t)w * HID + lane * 4);
        __half2 h01 = __floats2half2_rn(v.x, v.y);
        __half2 h23 = __floats2half2_rn(v.z, v.w);
        uint2 u;
        u.x = *(uint32_t*)&h01;
        u.y = *(uint32_t*)&h23;
        *(uint2*)(g_xh + (size_t)w * HID + lane * 4) = u;
    }

    long long m = g_is64 ? ((const long long*)hmv)[w]
                         : (long long)((const int*)hmv)[w];
    if (m != -1LL) {
        float4 v = ld_cs(hb + (size_t)w * HID + lane * 4);
        st_cs(out + (size_t)w * HID + lane * 4, v);
        if (dup)
            st_cs(out + (size_t)(w + num_node) * HID + lane * 4, v);
    } else if (lane == 0) {
        int slot = atomicAdd(&g_count, 1);
        g_active[slot] = w;
    }
}

// ---------------------------------------------------------------------------
// Aggregate: one warp per node; fp16 gathers staged through smem (cp.async,
// 2 edges per warp-instruction, two pipelined groups of 8 edges).
__device__ __forceinline__ void store_h(float4 a, size_t off) {
    __half2 h01 = __floats2half2_rn(a.x, a.y);
    __half2 h23 = __floats2half2_rn(a.z, a.w);
    uint2 uh;
    uh.x = *(uint32_t*)&h01;
    uh.y = *(uint32_t*)&h23;
    *(uint2*)((__half*)g_Ah + off) = uh;
}

#define ACC_CASE(r, a)                                                        \
    case r: a.x += v_.x; a.y += v_.y; a.z += v_.z; a.w += v_.w; break;

#define AGG_CHUNK 16
#define AGG_ROWH  (AGG_CHUNK * HID)      // halfs per warp buffer (2048)
#define AGG_THREADS 128
#define AGG_WARPS   (AGG_THREADS / 32)
#define AGG_SMEM (AGG_WARPS * AGG_ROWH * 2)   // 16384 bytes

__global__ __launch_bounds__(AGG_THREADS)
void aggregate_kernel(const void* __restrict__ ptrv,
                      const void* __restrict__ idxv,
                      const void* __restrict__ etv) {
    extern __shared__ __half hbuf[];    // 4 warps * 16 rows * 256B = 16 KB
    int w    = (int)((blockIdx.x * blockDim.x + threadIdx.x) >> 5);
    int lane = threadIdx.x & 31;
    if (w >= g_count) return;
    int is64 = g_is64;
    int node = g_active[w];

    long long p0, p1;
    if (is64) {
        p0 = ((const long long*)ptrv)[node];
        p1 = ((const long long*)ptrv)[node + 1];
    } else {
        p0 = ((const int*)ptrv)[node];
        p1 = ((const int*)ptrv)[node + 1];
    }

    __half*  mybuf = hbuf + (size_t)(threadIdx.x >> 5) * AGG_ROWH;
    uint32_t sm    = smem_u32(mybuf);
    const __half* xh = (const __half*)g_xh;

    float4 a0 = {0,0,0,0}, a1 = {0,0,0,0}, a2 = {0,0,0,0}, a3 = {0,0,0,0};
    float4 a4 = {0,0,0,0}, a5 = {0,0,0,0}, a6 = {0,0,0,0}, a7 = {0,0,0,0};

    int hlf = lane >> 4;        // which of 2 edges this half-warp stages
    int ch16 = lane & 15;       // 16B chunk within 256B row

    for (long long c0 = p0; c0 < p1; c0 += AGG_CHUNK) {
        int n = (int)((p1 - c0) < AGG_CHUNK ? (p1 - c0) : AGG_CHUNK);
        long long s_l = 0; int t_l = 0;
        if (lane < n) {
            long long e = c0 + lane;
            s_l = is64 ? ((const long long*)idxv)[e]
                       : (long long)((const int*)idxv)[e];
            t_l = is64 ? (int)((const long long*)etv)[e]
                       : ((const int*)etv)[e];
        }
        if (n == AGG_CHUNK) {
            #pragma unroll
            for (int it = 0; it < 4; it++) {
                int e = it * 2 + hlf;
                long long src = __shfl_sync(0xffffffffu, s_l, e);
                CP16(sm + (uint32_t)(e * 256 + ch16 * 16),
                     xh + (size_t)src * HID + ch16 * 8);
            }
            CP_COMMIT();
            #pragma unroll
            for (int it = 4; it < 8; it++) {
                int e = it * 2 + hlf;
                long long src = __shfl_sync(0xffffffffu, s_l, e);
                CP16(sm + (uint32_t)(e * 256 + ch16 * 16),
                     xh + (size_t)src * HID + ch16 * 8);
            }
            CP_COMMIT();
            CP_WAIT(1);
            __syncwarp();
            #pragma unroll
            for (int e = 0; e < 8; e++) {
                int ty = __shfl_sync(0xffffffffu, t_l, e);
                uint2 u = *(const uint2*)(mybuf + e * HID + lane * 4);
                float2 f01 = __half22float2(*(__half2*)&u.x);
                float2 f23 = __half22float2(*(__half2*)&u.y);
                float4 v_ = make_float4(f01.x, f01.y, f23.x, f23.y);
                switch (ty) {
                    ACC_CASE(0, a0) ACC_CASE(1, a1) ACC_CASE(2, a2) ACC_CASE(3, a3)
                    ACC_CASE(4, a4) ACC_CASE(5, a5) ACC_CASE(6, a6) ACC_CASE(7, a7)
                    default: break;
                }
            }
            CP_WAIT(0);
            __syncwarp();
            #pragma unroll
            for (int e = 8; e < 16; e++) {
                int ty = __shfl_sync(0xffffffffu, t_l, e);
                uint2 u = *(const uint2*)(mybuf + e * HID + lane * 4);
                float2 f01 = __half22float2(*(__half2*)&u.x);
                float2 f23 = __half22float2(*(__half2*)&u.y);
                float4 v_ = make_float4(f01.x, f01.y, f23.x, f23.y);
                switch (ty) {
                    ACC_CASE(0, a0) ACC_CASE(1, a1) ACC_CASE(2, a2) ACC_CASE(3, a3)
                    ACC_CASE(4, a4) ACC_CASE(5, a5) ACC_CASE(6, a6) ACC_CASE(7, a7)
                    default: break;
                }
            }
        } else {
            for (int e = 0; e < n; e++) {
                long long src = __shfl_sync(0xffffffffu, s_l, e);
                int ty       = __shfl_sync(0xffffffffu, t_l, e);
                uint2 u = *(const uint2*)(xh + (size_t)src * HID + lane * 4);
                float2 f01 = __half22float2(*(__half2*)&u.x);
                float2 f23 = __half22float2(*(__half2*)&u.y);
                float4 v_ = make_float4(f01.x, f01.y, f23.x, f23.y);
                switch (ty) {
                    ACC_CASE(0, a0) ACC_CASE(1, a1) ACC_CASE(2, a2) ACC_CASE(3, a3)
                    ACC_CASE(4, a4) ACC_CASE(5, a5) ACC_CASE(6, a6) ACC_CASE(7, a7)
                    default: break;
                }
            }
        }
        __syncwarp();
    }

    size_t base = (size_t)w * KDIM + lane * 4;
    store_h(a0, base + 0 * HID);  store_h(a1, base + 1 * HID);
    store_h(a2, base + 2 * HID);  store_h(a3, base + 3 * HID);
    store_h(a4, base + 4 * HID);  store_h(a5, base + 5 * HID);
    store_h(a6, base + 6 * HID);  store_h(a7, base + 7 * HID);
}

// ---------------------------------------------------------------------------
// mma.sync GEMM: [count,1024](A fp16) @ [1024,128](W fp16), single term.
// CTA 128x128, 128 threads (4 warps, 2m x 2n, warp 64x64), k-tile 64,
// 3-stage cp.async pipeline, 2 CTAs/SM, fragment software pipeline.
#define GBM 128
#define GBK 64
#define NT (KDIM / GBK)                // 16 k-tiles
#define TPA (GBM * GBK * 2)            // 16384 bytes A tile
#define TPB (HID * GBK * 2)            // 16384 bytes B tile
#define S_AH 0
#define S_BH TPA
#define STAGE_B (TPA + TPB)            // 32768 per stage
#define NSTG 3
#define SMEM_BYTES (NSTG * STAGE_B)    // 98304 per CTA (x2 CTAs = 196608)

// swizzled byte offset within a [rows][64 f16] tile (row stride 128B, SW128)
__device__ __forceinline__ uint32_t swz(uint32_t row, uint32_t chunk) {
    return row * 128u + ((chunk ^ (row & 7u)) << 4);
}

__global__ __launch_bounds__(128, 2)
void gemm_mma_kernel(const void* __restrict__ ptrv,
                     float* __restrict__ out,
                     int dup, int num_node) {
    extern __shared__ __align__(1024) char smem[];
    int count = g_count;
    int m0 = blockIdx.x * GBM;
    if (m0 >= count) return;

    uint32_t sb = smem_u32(smem);
    int t = threadIdx.x, wid = t >> 5, lane = t & 31;
    int wm = wid >> 1;                 // 0..1  (m block of 64)
    int wn = wid & 1;                  // 0..1  (n block of 64)

    const __half* pAh = (const __half*)g_Ah;
    const __half* pWh = (const __half*)g_Wh;

    int ltile = lane >> 3, lrow = lane & 7;

    float acc[4][8][4];
    #pragma unroll
    for (int i = 0; i < 4; i++)
        #pragma unroll
        for (int j = 0; j < 8; j++)
            #pragma unroll
            for (int q = 0; q < 4; q++) acc[i][j][q] = 0.f;

    // double-buffered fragments
    uint32_t ah[2][4];      // A: one m16 frag per buffer
    uint32_t bh[2][4][4];   // B: 4 n16 frags per buffer

    auto load_stage = [&](int kt) {
        uint32_t stg = sb + (uint32_t)(kt % NSTG) * STAGE_B;
        size_t kofs = (size_t)kt * GBK;
        #pragma unroll
        for (int i = 0; i < 8; i++) {
            int id  = t + i * 128;
            int row = id >> 3;
            int c   = id & 7;
            uint32_t sw = swz(row, c);
            size_t ga = (size_t)(m0 + row) * KDIM + kofs + c * 8;
            CP16(stg + S_AH + sw, pAh + ga);
        }
        #pragma unroll
        for (int i = 0; i < 8; i++) {
            int id  = t + i * 128;
            int row = id >> 3;
            int c   = id & 7;
            uint32_t sw = swz(row, c);
            size_t gw = (size_t)row * KDIM + kofs + c * 8;
            CP16(stg + S_BH + sw, pWh + gw);
        }
        CP_COMMIT();
    };

    auto ldA = [&](int buf, uint32_t stg, int cch, int mf) {
        uint32_t r = wm * 64 + mf * 16 + (ltile & 1) * 8 + lrow;
        LDSM4(ah[buf], stg + S_AH + swz(r, (uint32_t)cch));
    };
    auto ldB = [&](int buf, uint32_t stg, int cch) {
        #pragma unroll
        for (int j = 0; j < 4; j++) {
            uint32_t r = wn * 64 + j * 16 + (ltile & 1) * 8 + lrow;
            LDSM4(bh[buf][j], stg + S_BH + swz(r, (uint32_t)cch));
        }
    };

    load_stage(0);
    load_stage(1);

    int ab = 0, bb = 0;
    for (int kt = 0; kt < NT; kt++) {
        if (kt + 2 < NT) { CP_WAIT(1); }          // stage kt complete
        else             { CP_WAIT(0); }          // drain at tail
        __syncthreads();                          // all warps past mma(kt-1)
        if (kt + 2 < NT) load_stage(kt + 2);      // reuse buf (kt-1)%3: safe

        uint32_t stg = sb + (uint32_t)(kt % NSTG) * STAGE_B;
        int cch0 = 0 * 2 + (ltile >> 1);
        ldB(bb, stg, cch0);
        ldA(ab, stg, cch0, 0);

        #pragma unroll
        for (int ks = 0; ks < 4; ks++) {
            #pragma unroll
            for (int mf = 0; mf < 4; mf++) {
                // prefetch next fragments before consuming current
                if (mf < 3) {
                    ldA(ab ^ 1, stg, ks * 2 + (ltile >> 1), mf + 1);
                } else if (ks < 3) {
                    int cchn = (ks + 1) * 2 + (ltile >> 1);
                    ldB(bb ^ 1, stg, cchn);
                    ldA(ab ^ 1, stg, cchn, 0);
                }
                #pragma unroll
                for (int nf = 0; nf < 8; nf++) {
                    int hj = nf >> 1, ho = nf & 1;
                    MMA16816F16(acc[mf][nf], ah[ab],
                                bh[bb][hj][ho], bh[bb][hj][ho + 2]);
                }
                ab ^= 1;
            }
            bb ^= 1;
        }
    }

    // ---- epilogue: 1/deg scale + scatter (streaming stores) ----
    int g  = lane >> 2;
    int tq = lane & 3;
    int is64 = g_is64;
    #pragma unroll
    for (int mf = 0; mf < 4; mf++) {
        int m_lo = m0 + wm * 64 + mf * 16 + g;       // rows g and g+8
        #pragma unroll
        for (int half = 0; half < 2; half++) {
            int m = m_lo + half * 8;
            if (m >= count) continue;
            int node = g_active[m];
            long long d;
            if (is64)
                d = ((const long long*)ptrv)[node + 1] - ((const long long*)ptrv)[node];
            else
                d = (long long)(((const int*)ptrv)[node + 1] - ((const int*)ptrv)[node]);
            float inv = 1.0f / (float)d;
            #pragma unroll
            for (int nf = 0; nf < 8; nf++) {
                float2 v;
                v.x = acc[mf][nf][half * 2 + 0] * inv;
                v.y = acc[mf][nf][half * 2 + 1] * inv;
                size_t co = (size_t)node * HID + wn * 64 + nf * 8 + tq * 2;
                st_cs2(out + co, v);
                if (dup)
                    st_cs2(out + co + (size_t)num_node * HID, v);
            }
        }
    }
}

// ---------------------------------------------------------------------------
extern "C" void kernel_launch(void* const* d_in, const int* in_sizes, int n_in,
                              void* d_out, int out_size) {
    const float* x  = (const float*)d_in[0];
    const float* W  = (const float*)d_in[1];   // [8,128,128] == [1024,128]
    const void*  pt = d_in[2];
    const void*  ix = d_in[3];
    const void*  et = d_in[4];
    const void*  hm = d_in[5];
    const float* hb = (const float*)d_in[6];
    float* out = (float*)d_out;

    int num_node = in_sizes[0] / HID;
    long long need2 = 2LL * (long long)num_node * HID;
    int dup = ((long long)out_size >= need2) ? 1 : 0;

    cudaFuncSetAttribute(gemm_mma_kernel,
                         cudaFuncAttributeMaxDynamicSharedMemorySize, SMEM_BYTES);
    cudaFuncSetAttribute(aggregate_kernel,
                         cudaFuncAttributeMaxDynamicSharedMemorySize, AGG_SMEM);
    cudaFuncSetAttribute(aggregate_kernel,
                         cudaFuncAttributePreferredSharedMemoryCarveout,
                         cudaSharedmemCarveoutMaxShared);

    reset_kernel<<<1, 32>>>(pt);

    int warp_blocks = (num_node * 32 + 255) / 256;
    compact_history_kernel<<<warp_blocks, 256>>>(x, hm, hb, W, out, dup, num_node);

    int agg_blocks = (num_node * 32 + AGG_THREADS - 1) / AGG_THREADS;
    aggregate_kernel<<<agg_blocks, AGG_THREADS, AGG_SMEM>>>(pt, ix, et);

    gemm_mma_kernel<<<(num_node + GBM - 1) / GBM, 128, SMEM_BYTES>>>(
        pt, out, dup, num_node);
}